// round 1
// baseline (speedup 1.0000x reference)
#include <cuda_runtime.h>
#include <cstdint>

#define HG_L 16
#define HG_T (1u << 19)
#define HG_TMASK (HG_T - 1u)
#define WIDTH 64

#define P1 2654435761u
#define P2 805459861u
#define P3 3674653429u

// floor(16 * 1.5^l) for l = 0..15 (computed in double, matches numpy)
__constant__ float c_res[HG_L] = {
    16.f, 24.f, 36.f, 54.f, 81.f, 121.f, 182.f, 273.f,
    410.f, 615.f, 922.f, 1383.f, 2075.f, 3113.f, 4670.f, 7006.f
};

// Accumulate one level's (f0, f1) feature pair into the hidden layer h1[64],
// using W1 rows (row, row+1). W1s access is a warp-uniform broadcast LDS.128.
__device__ __forceinline__ void acc_l1(const float* __restrict__ W1s, int row,
                                       float f0, float f1, float* h1) {
    const float* w0 = W1s + row * WIDTH;
    const float* w1 = w0 + WIDTH;
#pragma unroll
    for (int j = 0; j < WIDTH; j += 4) {
        float4 a = *(const float4*)(w0 + j);
        float4 b = *(const float4*)(w1 + j);
        h1[j + 0] = fmaf(f0, a.x, fmaf(f1, b.x, h1[j + 0]));
        h1[j + 1] = fmaf(f0, a.y, fmaf(f1, b.y, h1[j + 1]));
        h1[j + 2] = fmaf(f0, a.z, fmaf(f1, b.z, h1[j + 2]));
        h1[j + 3] = fmaf(f0, a.w, fmaf(f1, b.w, h1[j + 3]));
    }
}

// 3D hash-grid encode, fused into layer-1 accumulation.
__device__ __forceinline__ void encode3(float x0, float x1, float x2,
                                        const float* __restrict__ tab,
                                        const float* __restrict__ W1s,
                                        int kbase, float* h1) {
#pragma unroll 1
    for (int l = 0; l < HG_L; l++) {
        float r = c_res[l];
        float px = x0 * r, py = x1 * r, pz = x2 * r;
        float fx = floorf(px), fy = floorf(py), fz = floorf(pz);
        float wx = px - fx, wy = py - fy, wz = pz - fz;

        uint32_t ax[2], ay[2], az[2];
        ax[0] = (uint32_t)fx;        ax[1] = ax[0] + 1u;
        ay[0] = (uint32_t)fy * P1;   ay[1] = ay[0] + P1;
        az[0] = (uint32_t)fz * P2;   az[1] = az[0] + P2;
        float vx[2] = {1.f - wx, wx};
        float vy[2] = {1.f - wy, wy};
        float vz[2] = {1.f - wz, wz};

        const float2* base = (const float2*)tab + (size_t)l * HG_T;
        float f0 = 0.f, f1 = 0.f;
#pragma unroll
        for (int c = 0; c < 8; c++) {
            const int bx = (c >> 2) & 1, by = (c >> 1) & 1, bz = c & 1;
            uint32_t id = (ax[bx] ^ ay[by] ^ az[bz]) & HG_TMASK;
            float2 f = __ldg(base + id);
            float wt = vx[bx] * vy[by] * vz[bz];
            f0 = fmaf(wt, f.x, f0);
            f1 = fmaf(wt, f.y, f1);
        }
        acc_l1(W1s, kbase + 2 * l, f0, f1, h1);
    }
}

// 4D hash-grid encode, fused into layer-1 accumulation.
__device__ __forceinline__ void encode4(float x0, float x1, float x2, float x3,
                                        const float* __restrict__ tab,
                                        const float* __restrict__ W1s,
                                        int kbase, float* h1) {
#pragma unroll 1
    for (int l = 0; l < HG_L; l++) {
        float r = c_res[l];
        float px = x0 * r, py = x1 * r, pz = x2 * r, pw = x3 * r;
        float fx = floorf(px), fy = floorf(py), fz = floorf(pz), fw = floorf(pw);
        float wx = px - fx, wy = py - fy, wz = pz - fz, ww = pw - fw;

        uint32_t ax[2], ay[2], az[2], aw[2];
        ax[0] = (uint32_t)fx;        ax[1] = ax[0] + 1u;
        ay[0] = (uint32_t)fy * P1;   ay[1] = ay[0] + P1;
        az[0] = (uint32_t)fz * P2;   az[1] = az[0] + P2;
        aw[0] = (uint32_t)fw * P3;   aw[1] = aw[0] + P3;
        float vx[2] = {1.f - wx, wx};
        float vy[2] = {1.f - wy, wy};
        float vz[2] = {1.f - wz, wz};
        float vw[2] = {1.f - ww, ww};

        const float2* base = (const float2*)tab + (size_t)l * HG_T;
        float f0 = 0.f, f1 = 0.f;
#pragma unroll
        for (int c = 0; c < 16; c++) {
            const int bx = (c >> 3) & 1, by = (c >> 2) & 1, bz = (c >> 1) & 1, bw = c & 1;
            uint32_t id = (ax[bx] ^ ay[by] ^ az[bz] ^ aw[bw]) & HG_TMASK;
            float2 f = __ldg(base + id);
            float wt = (vx[bx] * vy[by]) * (vz[bz] * vw[bw]);
            f0 = fmaf(wt, f.x, f0);
            f1 = fmaf(wt, f.y, f1);
        }
        acc_l1(W1s, kbase + 2 * l, f0, f1, h1);
    }
}

__global__ __launch_bounds__(256)
void hashgrid_mlp_kernel(const float* __restrict__ fc,
                         const float* __restrict__ fn,
                         const float* __restrict__ pe,
                         const float* __restrict__ pos_tab,
                         const float* __restrict__ nrm_tab,
                         const float* __restrict__ pose_tab,
                         const float* __restrict__ W1,
                         const float* __restrict__ W2,
                         const float* __restrict__ W3,
                         float* __restrict__ out, int n) {
    __shared__ float W1s[96 * WIDTH];       // 24 KB, as-is [96][64]
    __shared__ float W2Ts[WIDTH * WIDTH];   // 16 KB, transposed: W2Ts[j][k] = W2[k][j]
    __shared__ float W3s[WIDTH * 9];        // 2.25 KB, as-is [64][9]

    const int tid = threadIdx.x;
    for (int i = tid; i < 96 * WIDTH; i += 256) W1s[i] = W1[i];
    for (int i = tid; i < WIDTH * WIDTH; i += 256) {
        int k = i >> 6, j = i & 63;
        W2Ts[j * WIDTH + k] = W2[i];
    }
    for (int i = tid; i < WIDTH * 9; i += 256) W3s[i] = W3[i];
    __syncthreads();

    const int idx = blockIdx.x * 256 + tid;
    if (idx >= n) return;

    float h1[WIDTH];
#pragma unroll
    for (int j = 0; j < WIDTH; j++) h1[j] = 0.f;

    // --- three fused hash-grid encodes + MLP layer 1 ---
    {
        float x0 = fc[(size_t)idx * 3 + 0];
        float x1 = fc[(size_t)idx * 3 + 1];
        float x2 = fc[(size_t)idx * 3 + 2];
        encode3(x0, x1, x2, pos_tab, W1s, 0, h1);
    }
    {
        float x0 = fn[(size_t)idx * 3 + 0];
        float x1 = fn[(size_t)idx * 3 + 1];
        float x2 = fn[(size_t)idx * 3 + 2];
        encode3(x0, x1, x2, nrm_tab, W1s, 32, h1);
    }
    {
        float x0 = pe[(size_t)idx * 4 + 0];
        float x1 = pe[(size_t)idx * 4 + 1];
        float x2 = pe[(size_t)idx * 4 + 2];
        float x3 = pe[(size_t)idx * 4 + 3];
        encode4(x0, x1, x2, x3, pose_tab, W1s, 64, h1);
    }

    // --- relu(layer 1) ---
#pragma unroll
    for (int k = 0; k < WIDTH; k++) h1[k] = fmaxf(h1[k], 0.f);

    // --- layers 2 + 3 streamed: never materialize h2 as an indexed array ---
    float acc[9];
#pragma unroll
    for (int o = 0; o < 9; o++) acc[o] = 0.f;

#pragma unroll 1
    for (int j = 0; j < WIDTH; j++) {
        const float* wr = W2Ts + j * WIDTH;
        float s0 = 0.f, s1 = 0.f, s2 = 0.f, s3 = 0.f;
#pragma unroll
        for (int k = 0; k < WIDTH; k += 4) {
            float4 a = *(const float4*)(wr + k);
            s0 = fmaf(h1[k + 0], a.x, s0);
            s1 = fmaf(h1[k + 1], a.y, s1);
            s2 = fmaf(h1[k + 2], a.z, s2);
            s3 = fmaf(h1[k + 3], a.w, s3);
        }
        float s = fmaxf((s0 + s1) + (s2 + s3), 0.f);
        const float* w3 = W3s + j * 9;
#pragma unroll
        for (int o = 0; o < 9; o++) acc[o] = fmaf(s, w3[o], acc[o]);
    }

    float* op = out + (size_t)idx * 9;
#pragma unroll
    for (int o = 0; o < 9; o++) op[o] = acc[o];
}

extern "C" void kernel_launch(void* const* d_in, const int* in_sizes, int n_in,
                              void* d_out, int out_size) {
    const float* fc = (const float*)d_in[0];   // face_centers [N,3]
    const float* fn = (const float*)d_in[1];   // face_normals [N,3]
    const float* pe = (const float*)d_in[2];   // pose_extended [N,4]
    const float* pt = (const float*)d_in[3];   // pos_table [L,T,F]
    const float* nt = (const float*)d_in[4];   // normal_table
    const float* qt = (const float*)d_in[5];   // pose_table
    const float* W1 = (const float*)d_in[6];   // [96,64]
    const float* W2 = (const float*)d_in[7];   // [64,64]
    const float* W3 = (const float*)d_in[8];   // [64,9]
    float* out = (float*)d_out;

    const int n = in_sizes[0] / 3;
    const int threads = 256;
    const int blocks = (n + threads - 1) / threads;
    hashgrid_mlp_kernel<<<blocks, threads>>>(fc, fn, pe, pt, nt, qt, W1, W2, W3, out, n);
}